// round 1
// baseline (speedup 1.0000x reference)
#include <cuda_runtime.h>
#include <math.h>

// Problem dims (fixed per reference)
#define BATCH 8
#define SEQ   2048
#define DIM   1024
#define MTOT  (BATCH * SEQ)          // 16384

// SGEMM tiling
#define BM 128
#define BN 128
#define BK 8
#define TM 8
#define TN 8
#define NTHREADS 256                 // (BM/TM)*(BN/TN)

// -------- scratch (no cudaMalloc allowed) --------
__device__ float g_q[(size_t)MTOT * DIM];
__device__ float g_k[(size_t)MTOT * DIM];
__device__ float g_v[(size_t)MTOT * DIM];
__device__ float g_g[(size_t)MTOT * DIM];
__device__ float g_s[(size_t)BATCH * SEQ * SEQ];
__device__ float g_c[(size_t)MTOT * DIM];

// ---------------------------------------------------------------------------
// Generic batched SGEMM: C[b] = A[b] (MxK, row-major) * op(B[b]) (+ bias)
//   TRANS_B = false: B is [K,N] row-major
//   TRANS_B = true : B is [N,K] row-major (computes A * B^T)
// All of M, N multiples of 128; K multiple of 8 (true here: 1024/2048).
// ---------------------------------------------------------------------------
template <bool TRANS_B, bool BIAS>
__global__ __launch_bounds__(NTHREADS)
void sgemm_kernel(const float* __restrict__ A, const float* __restrict__ B,
                  const float* __restrict__ bias, float* __restrict__ C,
                  int M, int N, int K,
                  long long sA, long long sB, long long sC)
{
    __shared__ float As[BK][BM];
    __shared__ float Bs[BK][BN];

    const int b = blockIdx.z;
    A += (long long)b * sA;
    B += (long long)b * sB;
    C += (long long)b * sC;

    const int m0 = blockIdx.y * BM;
    const int n0 = blockIdx.x * BN;
    const int t  = threadIdx.x;

    // A loader: 128 rows x 8 cols, one float4 per thread along K
    const int arow = t >> 1;
    const int acol = (t & 1) * 4;
    // B loader
    const int btr_row = t >> 1;          // TRANS_B: n-index
    const int btr_col = (t & 1) * 4;     // TRANS_B: k-index
    const int bkn_row = t >> 5;          // !TRANS_B: k-index
    const int bkn_col = (t & 31) * 4;    // !TRANS_B: n-index

    const int ty = t >> 4;               // 0..15
    const int tx = t & 15;               // 0..15

    float acc[TM][TN];
    #pragma unroll
    for (int i = 0; i < TM; i++)
        #pragma unroll
        for (int j = 0; j < TN; j++) acc[i][j] = 0.0f;

    for (int k0 = 0; k0 < K; k0 += BK) {
        // load A tile (transposed into As[k][m])
        float4 av = *reinterpret_cast<const float4*>(
            &A[(long long)(m0 + arow) * K + k0 + acol]);
        As[acol + 0][arow] = av.x;
        As[acol + 1][arow] = av.y;
        As[acol + 2][arow] = av.z;
        As[acol + 3][arow] = av.w;

        if (TRANS_B) {
            float4 bv = *reinterpret_cast<const float4*>(
                &B[(long long)(n0 + btr_row) * K + k0 + btr_col]);
            Bs[btr_col + 0][btr_row] = bv.x;
            Bs[btr_col + 1][btr_row] = bv.y;
            Bs[btr_col + 2][btr_row] = bv.z;
            Bs[btr_col + 3][btr_row] = bv.w;
        } else {
            float4 bv = *reinterpret_cast<const float4*>(
                &B[(long long)(k0 + bkn_row) * N + n0 + bkn_col]);
            *reinterpret_cast<float4*>(&Bs[bkn_row][bkn_col]) = bv;
        }
        __syncthreads();

        #pragma unroll
        for (int kk = 0; kk < BK; ++kk) {
            float a[TM], bb[TN];
            #pragma unroll
            for (int i = 0; i < TM; i++) a[i] = As[kk][ty * TM + i];
            #pragma unroll
            for (int j = 0; j < TN; j++) bb[j] = Bs[kk][tx * TN + j];
            #pragma unroll
            for (int i = 0; i < TM; i++)
                #pragma unroll
                for (int j = 0; j < TN; j++)
                    acc[i][j] = fmaf(a[i], bb[j], acc[i][j]);
        }
        __syncthreads();
    }

    #pragma unroll
    for (int i = 0; i < TM; i++) {
        const int m = m0 + ty * TM + i;
        #pragma unroll
        for (int j = 0; j < TN; j += 4) {
            const int n = n0 + tx * TN + j;
            float4 v;
            v.x = acc[i][j + 0];
            v.y = acc[i][j + 1];
            v.z = acc[i][j + 2];
            v.w = acc[i][j + 3];
            if (BIAS) {
                v.x += bias[n + 0];
                v.y += bias[n + 1];
                v.z += bias[n + 2];
                v.w += bias[n + 3];
            }
            *reinterpret_cast<float4*>(&C[(long long)m * N + n]) = v;
        }
    }
}

// ---------------------------------------------------------------------------
// Row softmax over rows of length SEQ (2048). One block (256 threads) per row.
// ---------------------------------------------------------------------------
__global__ __launch_bounds__(256)
void softmax_kernel(float* __restrict__ S)
{
    const int n = SEQ;
    float* p = S + (long long)blockIdx.x * n;
    const int tid = threadIdx.x;

    __shared__ float red[8];

    float v[8];
    float mx = -1e30f;
    #pragma unroll
    for (int i = 0; i < 8; i++) {
        v[i] = p[i * 256 + tid];
        mx = fmaxf(mx, v[i]);
    }
    #pragma unroll
    for (int o = 16; o; o >>= 1) mx = fmaxf(mx, __shfl_xor_sync(0xffffffffu, mx, o));
    if ((tid & 31) == 0) red[tid >> 5] = mx;
    __syncthreads();
    mx = red[0];
    #pragma unroll
    for (int i = 1; i < 8; i++) mx = fmaxf(mx, red[i]);
    __syncthreads();

    float s = 0.0f;
    #pragma unroll
    for (int i = 0; i < 8; i++) {
        v[i] = expf(v[i] - mx);
        s += v[i];
    }
    #pragma unroll
    for (int o = 16; o; o >>= 1) s += __shfl_xor_sync(0xffffffffu, s, o);
    if ((tid & 31) == 0) red[tid >> 5] = s;
    __syncthreads();
    s = red[0];
    #pragma unroll
    for (int i = 1; i < 8; i++) s += red[i];

    const float inv = 1.0f / s;
    #pragma unroll
    for (int i = 0; i < 8; i++) p[i * 256 + tid] = v[i] * inv;
}

// ---------------------------------------------------------------------------
// ctx *= sigmoid(gate_pre), elementwise, float4-vectorized
// ---------------------------------------------------------------------------
__global__ __launch_bounds__(256)
void gate_kernel(float* __restrict__ ctx, const float* __restrict__ g)
{
    const long long i = (long long)blockIdx.x * blockDim.x + threadIdx.x;
    float4 c  = reinterpret_cast<float4*>(ctx)[i];
    float4 gg = reinterpret_cast<const float4*>(g)[i];
    c.x *= 1.0f / (1.0f + expf(-gg.x));
    c.y *= 1.0f / (1.0f + expf(-gg.y));
    c.z *= 1.0f / (1.0f + expf(-gg.z));
    c.w *= 1.0f / (1.0f + expf(-gg.w));
    reinterpret_cast<float4*>(ctx)[i] = c;
}

// ---------------------------------------------------------------------------
// launch
// ---------------------------------------------------------------------------
extern "C" void kernel_launch(void* const* d_in, const int* in_sizes, int n_in,
                              void* d_out, int out_size)
{
    (void)in_sizes; (void)n_in; (void)out_size;

    const float* queries = (const float*)d_in[0];
    const float* keys    = (const float*)d_in[1];
    const float* values  = (const float*)d_in[2];
    const float* Wq = (const float*)d_in[3];
    const float* bq = (const float*)d_in[4];
    const float* Wk = (const float*)d_in[5];
    const float* bk = (const float*)d_in[6];
    const float* Wv = (const float*)d_in[7];
    const float* bv = (const float*)d_in[8];
    const float* Wg = (const float*)d_in[9];
    const float* bg = (const float*)d_in[10];
    const float* Wo = (const float*)d_in[11];
    const float* bo = (const float*)d_in[12];
    float* out = (float*)d_out;

    float *qb, *kb, *vb, *gb, *sb, *cb;
    cudaGetSymbolAddress((void**)&qb, g_q);
    cudaGetSymbolAddress((void**)&kb, g_k);
    cudaGetSymbolAddress((void**)&vb, g_v);
    cudaGetSymbolAddress((void**)&gb, g_g);
    cudaGetSymbolAddress((void**)&sb, g_s);
    cudaGetSymbolAddress((void**)&cb, g_c);

    // 1) Projections: [16384,1024] = [16384,1024] @ [1024,1024] + bias
    {
        dim3 grid(DIM / BN, MTOT / BM, 1);
        sgemm_kernel<false, true><<<grid, NTHREADS>>>(queries, Wq, bq, qb,
                                                      MTOT, DIM, DIM, 0, 0, 0);
        sgemm_kernel<false, true><<<grid, NTHREADS>>>(keys, Wk, bk, kb,
                                                      MTOT, DIM, DIM, 0, 0, 0);
        sgemm_kernel<false, true><<<grid, NTHREADS>>>(values, Wv, bv, vb,
                                                      MTOT, DIM, DIM, 0, 0, 0);
        sgemm_kernel<false, true><<<grid, NTHREADS>>>(queries, Wg, bg, gb,
                                                      MTOT, DIM, DIM, 0, 0, 0);
    }

    // 2) scores[b] = q[b] @ k[b]^T   (batched, TRANS_B)
    {
        dim3 grid(SEQ / BN, SEQ / BM, BATCH);
        sgemm_kernel<true, false><<<grid, NTHREADS>>>(
            qb, kb, nullptr, sb, SEQ, SEQ, DIM,
            (long long)SEQ * DIM, (long long)SEQ * DIM, (long long)SEQ * SEQ);
    }

    // 3) row softmax over 8*2048 rows of length 2048
    softmax_kernel<<<BATCH * SEQ, 256>>>(sb);

    // 4) ctx[b] = attn[b] @ v[b]
    {
        dim3 grid(DIM / BN, SEQ / BM, BATCH);
        sgemm_kernel<false, false><<<grid, NTHREADS>>>(
            sb, vb, nullptr, cb, SEQ, DIM, SEQ,
            (long long)SEQ * SEQ, (long long)SEQ * DIM, (long long)SEQ * DIM);
    }

    // 5) ctx *= sigmoid(gate_pre)
    {
        const long long total4 = (long long)MTOT * DIM / 4;
        gate_kernel<<<(unsigned)(total4 / 256), 256>>>(cb, gb);
    }

    // 6) out = gated_ctx @ Wo + bo
    {
        dim3 grid(DIM / BN, MTOT / BM, 1);
        sgemm_kernel<false, true><<<grid, NTHREADS>>>(cb, Wo, bo, out,
                                                      MTOT, DIM, DIM, 0, 0, 0);
    }
}

// round 2
// speedup vs baseline: 1.0011x; 1.0011x over previous
#include <cuda_runtime.h>
#include <math.h>

// Problem dims (fixed per reference)
#define BATCH 8
#define SEQ   2048
#define DIM   1024
#define MTOT  (BATCH * SEQ)          // 16384

// SGEMM tiling
#define BM 128
#define BN 128
#define BK 8
#define TM 8
#define TN 8
#define NTHREADS 256                 // (BM/TM)*(BN/TN)

// -------- scratch (no cudaMalloc allowed) --------
__device__ float g_q[(size_t)MTOT * DIM];
__device__ float g_k[(size_t)MTOT * DIM];
__device__ float g_v[(size_t)MTOT * DIM];
__device__ float g_g[(size_t)MTOT * DIM];
__device__ float g_s[(size_t)BATCH * SEQ * SEQ];
__device__ float g_c[(size_t)MTOT * DIM];

// ---------------------------------------------------------------------------
// Generic batched SGEMM: C[b] = A[b] (MxK, row-major) * op(B[b]) (+ bias)
//   TRANS_B = false: B is [K,N] row-major
//   TRANS_B = true : B is [N,K] row-major (computes A * B^T)
// All of M, N multiples of 128; K multiple of 8 (true here: 1024/2048).
// ---------------------------------------------------------------------------
template <bool TRANS_B, bool BIAS>
__global__ __launch_bounds__(NTHREADS)
void sgemm_kernel(const float* __restrict__ A, const float* __restrict__ B,
                  const float* __restrict__ bias, float* __restrict__ C,
                  int M, int N, int K,
                  long long sA, long long sB, long long sC)
{
    __shared__ float As[BK][BM];
    __shared__ float Bs[BK][BN];

    const int b = blockIdx.z;
    A += (long long)b * sA;
    B += (long long)b * sB;
    C += (long long)b * sC;

    const int m0 = blockIdx.y * BM;
    const int n0 = blockIdx.x * BN;
    const int t  = threadIdx.x;

    // A loader: 128 rows x 8 cols, one float4 per thread along K
    const int arow = t >> 1;
    const int acol = (t & 1) * 4;
    // B loader
    const int btr_row = t >> 1;          // TRANS_B: n-index
    const int btr_col = (t & 1) * 4;     // TRANS_B: k-index
    const int bkn_row = t >> 5;          // !TRANS_B: k-index
    const int bkn_col = (t & 31) * 4;    // !TRANS_B: n-index

    const int ty = t >> 4;               // 0..15
    const int tx = t & 15;               // 0..15

    float acc[TM][TN];
    #pragma unroll
    for (int i = 0; i < TM; i++)
        #pragma unroll
        for (int j = 0; j < TN; j++) acc[i][j] = 0.0f;

    for (int k0 = 0; k0 < K; k0 += BK) {
        // load A tile (transposed into As[k][m])
        float4 av = *reinterpret_cast<const float4*>(
            &A[(long long)(m0 + arow) * K + k0 + acol]);
        As[acol + 0][arow] = av.x;
        As[acol + 1][arow] = av.y;
        As[acol + 2][arow] = av.z;
        As[acol + 3][arow] = av.w;

        if (TRANS_B) {
            float4 bv = *reinterpret_cast<const float4*>(
                &B[(long long)(n0 + btr_row) * K + k0 + btr_col]);
            Bs[btr_col + 0][btr_row] = bv.x;
            Bs[btr_col + 1][btr_row] = bv.y;
            Bs[btr_col + 2][btr_row] = bv.z;
            Bs[btr_col + 3][btr_row] = bv.w;
        } else {
            float4 bv = *reinterpret_cast<const float4*>(
                &B[(long long)(k0 + bkn_row) * N + n0 + bkn_col]);
            *reinterpret_cast<float4*>(&Bs[bkn_row][bkn_col]) = bv;
        }
        __syncthreads();

        #pragma unroll
        for (int kk = 0; kk < BK; ++kk) {
            float a[TM], bb[TN];
            #pragma unroll
            for (int i = 0; i < TM; i++) a[i] = As[kk][ty * TM + i];
            #pragma unroll
            for (int j = 0; j < TN; j++) bb[j] = Bs[kk][tx * TN + j];
            #pragma unroll
            for (int i = 0; i < TM; i++)
                #pragma unroll
                for (int j = 0; j < TN; j++)
                    acc[i][j] = fmaf(a[i], bb[j], acc[i][j]);
        }
        __syncthreads();
    }

    #pragma unroll
    for (int i = 0; i < TM; i++) {
        const int m = m0 + ty * TM + i;
        #pragma unroll
        for (int j = 0; j < TN; j += 4) {
            const int n = n0 + tx * TN + j;
            float4 v;
            v.x = acc[i][j + 0];
            v.y = acc[i][j + 1];
            v.z = acc[i][j + 2];
            v.w = acc[i][j + 3];
            if (BIAS) {
                v.x += bias[n + 0];
                v.y += bias[n + 1];
                v.z += bias[n + 2];
                v.w += bias[n + 3];
            }
            *reinterpret_cast<float4*>(&C[(long long)m * N + n]) = v;
        }
    }
}

// ---------------------------------------------------------------------------
// Row softmax over rows of length SEQ (2048). One block (256 threads) per row.
// ---------------------------------------------------------------------------
__global__ __launch_bounds__(256)
void softmax_kernel(float* __restrict__ S)
{
    const int n = SEQ;
    float* p = S + (long long)blockIdx.x * n;
    const int tid = threadIdx.x;

    __shared__ float red[8];

    float v[8];
    float mx = -1e30f;
    #pragma unroll
    for (int i = 0; i < 8; i++) {
        v[i] = p[i * 256 + tid];
        mx = fmaxf(mx, v[i]);
    }
    #pragma unroll
    for (int o = 16; o; o >>= 1) mx = fmaxf(mx, __shfl_xor_sync(0xffffffffu, mx, o));
    if ((tid & 31) == 0) red[tid >> 5] = mx;
    __syncthreads();
    mx = red[0];
    #pragma unroll
    for (int i = 1; i < 8; i++) mx = fmaxf(mx, red[i]);
    __syncthreads();

    float s = 0.0f;
    #pragma unroll
    for (int i = 0; i < 8; i++) {
        v[i] = expf(v[i] - mx);
        s += v[i];
    }
    #pragma unroll
    for (int o = 16; o; o >>= 1) s += __shfl_xor_sync(0xffffffffu, s, o);
    if ((tid & 31) == 0) red[tid >> 5] = s;
    __syncthreads();
    s = red[0];
    #pragma unroll
    for (int i = 1; i < 8; i++) s += red[i];

    const float inv = 1.0f / s;
    #pragma unroll
    for (int i = 0; i < 8; i++) p[i * 256 + tid] = v[i] * inv;
}

// ---------------------------------------------------------------------------
// ctx *= sigmoid(gate_pre), elementwise, float4-vectorized
// ---------------------------------------------------------------------------
__global__ __launch_bounds__(256)
void gate_kernel(float* __restrict__ ctx, const float* __restrict__ g)
{
    const long long i = (long long)blockIdx.x * blockDim.x + threadIdx.x;
    float4 c  = reinterpret_cast<float4*>(ctx)[i];
    float4 gg = reinterpret_cast<const float4*>(g)[i];
    c.x *= 1.0f / (1.0f + expf(-gg.x));
    c.y *= 1.0f / (1.0f + expf(-gg.y));
    c.z *= 1.0f / (1.0f + expf(-gg.z));
    c.w *= 1.0f / (1.0f + expf(-gg.w));
    reinterpret_cast<float4*>(ctx)[i] = c;
}

// ---------------------------------------------------------------------------
// launch
// ---------------------------------------------------------------------------
extern "C" void kernel_launch(void* const* d_in, const int* in_sizes, int n_in,
                              void* d_out, int out_size)
{
    (void)in_sizes; (void)n_in; (void)out_size;

    const float* queries = (const float*)d_in[0];
    const float* keys    = (const float*)d_in[1];
    const float* values  = (const float*)d_in[2];
    const float* Wq = (const float*)d_in[3];
    const float* bq = (const float*)d_in[4];
    const float* Wk = (const float*)d_in[5];
    const float* bk = (const float*)d_in[6];
    const float* Wv = (const float*)d_in[7];
    const float* bv = (const float*)d_in[8];
    const float* Wg = (const float*)d_in[9];
    const float* bg = (const float*)d_in[10];
    const float* Wo = (const float*)d_in[11];
    const float* bo = (const float*)d_in[12];
    float* out = (float*)d_out;

    float *qb, *kb, *vb, *gb, *sb, *cb;
    cudaGetSymbolAddress((void**)&qb, g_q);
    cudaGetSymbolAddress((void**)&kb, g_k);
    cudaGetSymbolAddress((void**)&vb, g_v);
    cudaGetSymbolAddress((void**)&gb, g_g);
    cudaGetSymbolAddress((void**)&sb, g_s);
    cudaGetSymbolAddress((void**)&cb, g_c);

    // 1) Projections: [16384,1024] = [16384,1024] @ [1024,1024] + bias
    {
        dim3 grid(DIM / BN, MTOT / BM, 1);
        sgemm_kernel<false, true><<<grid, NTHREADS>>>(queries, Wq, bq, qb,
                                                      MTOT, DIM, DIM, 0, 0, 0);
        sgemm_kernel<false, true><<<grid, NTHREADS>>>(keys, Wk, bk, kb,
                                                      MTOT, DIM, DIM, 0, 0, 0);
        sgemm_kernel<false, true><<<grid, NTHREADS>>>(values, Wv, bv, vb,
                                                      MTOT, DIM, DIM, 0, 0, 0);
        sgemm_kernel<false, true><<<grid, NTHREADS>>>(queries, Wg, bg, gb,
                                                      MTOT, DIM, DIM, 0, 0, 0);
    }

    // 2) scores[b] = q[b] @ k[b]^T   (batched, TRANS_B)
    {
        dim3 grid(SEQ / BN, SEQ / BM, BATCH);
        sgemm_kernel<true, false><<<grid, NTHREADS>>>(
            qb, kb, nullptr, sb, SEQ, SEQ, DIM,
            (long long)SEQ * DIM, (long long)SEQ * DIM, (long long)SEQ * SEQ);
    }

    // 3) row softmax over 8*2048 rows of length 2048
    softmax_kernel<<<BATCH * SEQ, 256>>>(sb);

    // 4) ctx[b] = attn[b] @ v[b]
    {
        dim3 grid(DIM / BN, SEQ / BM, BATCH);
        sgemm_kernel<false, false><<<grid, NTHREADS>>>(
            sb, vb, nullptr, cb, SEQ, DIM, SEQ,
            (long long)SEQ * SEQ, (long long)SEQ * DIM, (long long)SEQ * DIM);
    }

    // 5) ctx *= sigmoid(gate_pre)
    {
        const long long total4 = (long long)MTOT * DIM / 4;
        gate_kernel<<<(unsigned)(total4 / 256), 256>>>(cb, gb);
    }

    // 6) out = gated_ctx @ Wo + bo
    {
        dim3 grid(DIM / BN, MTOT / BM, 1);
        sgemm_kernel<false, true><<<grid, NTHREADS>>>(cb, Wo, bo, out,
                                                      MTOT, DIM, DIM, 0, 0, 0);
    }
}

// round 4
// speedup vs baseline: 2.9318x; 2.9284x over previous
#include <cuda_runtime.h>
#include <cuda_bf16.h>
#include <math.h>
#include <stdint.h>

#define BATCH 8
#define SEQ   2048
#define DIM   1024
#define MTOT  (BATCH * SEQ)   // 16384

#define NBF ((size_t)MTOT * DIM)         // 16,777,216
#define NSC ((size_t)BATCH * SEQ * SEQ)  // 33,554,432

// ===================== scratch (no cudaMalloc allowed) =====================
__device__ __align__(1024) __nv_bfloat16 g_Qh[NBF], g_Ql[NBF];   // split inputs
__device__ __align__(1024) __nv_bfloat16 g_Kh[NBF], g_Kl[NBF];
__device__ __align__(1024) __nv_bfloat16 g_Vh[NBF], g_Vl[NBF];
__device__ __align__(1024) __nv_bfloat16 g_qph[NBF], g_qpl[NBF]; // q projection
__device__ __align__(1024) __nv_bfloat16 g_kph[NBF], g_kpl[NBF]; // k projection
__device__ __align__(1024) __nv_bfloat16 g_vph[NBF], g_vpl[NBF]; // v projection (row-major [s][d])
__device__ __align__(1024) __nv_bfloat16 g_gch[NBF], g_gcl[NBF]; // gated context
__device__ __align__(1024) __nv_bfloat16 g_ah[NSC], g_al[NSC];   // softmax(attn)
__device__ __align__(1024) __nv_bfloat16 g_W[10][DIM * DIM];     // W h/l x5, layout [k][n]
__device__ __align__(1024) float g_scores[NSC];
__device__ __align__(1024) float g_gpre[NBF];
__device__ __align__(1024) float g_ctx[NBF];

// ===================== PTX wrappers (baseline sm_80+ features only) =========
__device__ __forceinline__ uint32_t smem_u32(const void* p) {
    uint32_t a;
    asm("{ .reg .u64 t; cvta.to.shared.u64 t, %1; cvt.u32.u64 %0, t; }" : "=r"(a) : "l"(p));
    return a;
}
__device__ __forceinline__ void cpa16(uint32_t dst, const void* src) {
    asm volatile("cp.async.cg.shared.global [%0], [%1], 16;" :: "r"(dst), "l"(src));
}
__device__ __forceinline__ void cp_commit() {
    asm volatile("cp.async.commit_group;" ::: "memory");
}
template <int N>
__device__ __forceinline__ void cp_wait() {
    asm volatile("cp.async.wait_group %0;" :: "n"(N) : "memory");
}
__device__ __forceinline__ void ldm4(uint32_t r[4], uint32_t addr) {
    asm volatile("ldmatrix.sync.aligned.m8n8.x4.shared.b16 {%0,%1,%2,%3}, [%4];"
                 : "=r"(r[0]), "=r"(r[1]), "=r"(r[2]), "=r"(r[3]) : "r"(addr));
}
__device__ __forceinline__ void ldm4t(uint32_t r[4], uint32_t addr) {
    asm volatile("ldmatrix.sync.aligned.m8n8.x4.trans.shared.b16 {%0,%1,%2,%3}, [%4];"
                 : "=r"(r[0]), "=r"(r[1]), "=r"(r[2]), "=r"(r[3]) : "r"(addr));
}
__device__ __forceinline__ void mma16816(float c[4],
                                         const uint32_t a[4],
                                         uint32_t b0, uint32_t b1) {
    asm volatile(
        "mma.sync.aligned.m16n8k16.row.col.f32.bf16.bf16.f32 "
        "{%0,%1,%2,%3}, {%4,%5,%6,%7}, {%8,%9}, {%0,%1,%2,%3};"
        : "+f"(c[0]), "+f"(c[1]), "+f"(c[2]), "+f"(c[3])
        : "r"(a[0]), "r"(a[1]), "r"(a[2]), "r"(a[3]), "r"(b0), "r"(b1));
}
__device__ __forceinline__ void split2(float x, __nv_bfloat16& h, __nv_bfloat16& l) {
    h = __float2bfloat16(x);
    l = __float2bfloat16(x - __bfloat162float(h));
}

// ===================== bf16x3 HMMA GEMM =====================
// D(128x128 tile) = A @ op(B), fp32 accumulate, via 3 MMA passes (hh + hl + lh).
// A: [m][k] row-major bf16 hi/lo.
// TRANSB=false: B stored [n][k] (computes A @ B^T over k).
// TRANSB=true : B stored [k][n].
// OMODE 0: fp32 out (+bias). OMODE 1: bf16 hi/lo pair out (+bias).
// M, N multiples of 128; K multiple of 32.
#define PA_E   40            // A / B-nontrans row pitch (elems): 32 data + 8 pad
#define PA_B   (PA_E * 2)    // 80 bytes
#define PBT_E  136           // B-trans row pitch (elems): 128 data + 8 pad
#define PBT_B  (PBT_E * 2)   // 272 bytes
#define MAT_BYTES   10240    // one operand matrix region per stage
#define STAGE_BYTES (4 * MAT_BYTES)           // Ah, Al, Bh, Bl
#define GEMM_SMEM   (2 * STAGE_BYTES)         // double buffered = 81920 B

template <bool TRANSB, int OMODE>
__global__ void __launch_bounds__(256)
hgemm(const __nv_bfloat16* __restrict__ gAh, const __nv_bfloat16* __restrict__ gAl,
      const __nv_bfloat16* __restrict__ gBh, const __nv_bfloat16* __restrict__ gBl,
      float* __restrict__ cf,
      __nv_bfloat16* __restrict__ ch, __nv_bfloat16* __restrict__ cl,
      const float* __restrict__ bias,
      int lda, int ldb, int ldc, int K,
      long long sa, long long sb, long long sc)
{
    extern __shared__ __align__(128) char smem[];
    const uint32_t sbase = smem_u32(smem);

    const int tid  = threadIdx.x;
    const int wid  = tid >> 5;
    const int lane = tid & 31;
    const int m0   = blockIdx.y * 128;
    const int n0   = blockIdx.x * 128;
    const int z    = blockIdx.z;

    gAh += (long long)z * sa;  gAl += (long long)z * sa;
    gBh += (long long)z * sb;  gBl += (long long)z * sb;

    const int wm0 = (wid >> 2) * 64;    // warp m offset within CTA tile
    const int wn0 = (wid & 3) * 32;     // warp n offset

    float acc[4][4][4];
    #pragma unroll
    for (int i = 0; i < 4; i++)
        #pragma unroll
        for (int j = 0; j < 4; j++)
            #pragma unroll
            for (int r = 0; r < 4; r++) acc[i][j][r] = 0.0f;

    const int nchunks = K >> 5;

    // ------- stage loader -------
    auto load_stage = [&](int s, int k0) {
        const uint32_t st = sbase + s * STAGE_BYTES;
        #pragma unroll
        for (int j = 0; j < 2; j++) {
            const int c = tid + 256 * j;
            {   // A hi/lo: 128 rows x 32 cols
                const int row = c >> 2, col = c & 3;
                const uint32_t so = st + row * PA_B + col * 16;
                const long long go = (long long)(m0 + row) * lda + k0 + col * 8;
                cpa16(so,             gAh + go);
                cpa16(so + MAT_BYTES, gAl + go);
            }
            if (TRANSB) {   // B: 32 rows (k) x 128 cols (n)
                const int row = c >> 4, col = c & 15;
                const uint32_t so = st + 2 * MAT_BYTES + row * PBT_B + col * 16;
                const long long go = (long long)(k0 + row) * ldb + n0 + col * 8;
                cpa16(so,             gBh + go);
                cpa16(so + MAT_BYTES, gBl + go);
            } else {        // B: 128 rows (n) x 32 cols (k)
                const int row = c >> 2, col = c & 3;
                const uint32_t so = st + 2 * MAT_BYTES + row * PA_B + col * 16;
                const long long go = (long long)(n0 + row) * ldb + k0 + col * 8;
                cpa16(so,             gBh + go);
                cpa16(so + MAT_BYTES, gBl + go);
            }
        }
    };

    // ------- compute one stage -------
    auto compute_stage = [&](int s) {
        const uint32_t ab = sbase + s * STAGE_BYTES;
        const uint32_t bb = ab + 2 * MAT_BYTES;
        #pragma unroll
        for (int ks = 0; ks < 32; ks += 16) {
            uint32_t ah[4][4], al[4][4];
            #pragma unroll
            for (int im = 0; im < 4; im++) {
                const uint32_t addr = ab
                    + (wm0 + im * 16 + (lane & 15)) * PA_B
                    + (ks + ((lane >> 4) << 3)) * 2;
                ldm4(ah[im], addr);
                ldm4(al[im], addr + MAT_BYTES);
            }
            uint32_t bh[4][2], bl[4][2];
            #pragma unroll
            for (int half = 0; half < 2; half++) {   // covers n-tiles 2*half, 2*half+1
                const int nb = wn0 + half * 16;
                uint32_t rh[4], rl[4];
                if (TRANSB) {
                    const int krow = ks + (lane & 7) + (((lane >> 3) & 1) << 3);
                    const int ncol = nb + ((lane >> 4) << 3);
                    const uint32_t addr = bb + krow * PBT_B + ncol * 2;
                    ldm4t(rh, addr);
                    ldm4t(rl, addr + MAT_BYTES);
                } else {
                    const int nrow = nb + (lane & 7) + ((lane >> 4) << 3);
                    const int kcol = ks + (((lane >> 3) & 1) << 3);
                    const uint32_t addr = bb + nrow * PA_B + kcol * 2;
                    ldm4(rh, addr);
                    ldm4(rl, addr + MAT_BYTES);
                }
                bh[2*half][0] = rh[0]; bh[2*half][1] = rh[1];
                bh[2*half+1][0] = rh[2]; bh[2*half+1][1] = rh[3];
                bl[2*half][0] = rl[0]; bl[2*half][1] = rl[1];
                bl[2*half+1][0] = rl[2]; bl[2*half+1][1] = rl[3];
            }
            #pragma unroll
            for (int im = 0; im < 4; im++)
                #pragma unroll
                for (int in = 0; in < 4; in++) {
                    mma16816(acc[im][in], ah[im], bh[in][0], bh[in][1]);
                    mma16816(acc[im][in], ah[im], bl[in][0], bl[in][1]);
                    mma16816(acc[im][in], al[im], bh[in][0], bh[in][1]);
                }
        }
    };

    // ------- pipeline -------
    load_stage(0, 0);
    cp_commit();
    for (int c = 0; c < nchunks; c++) {
        if (c + 1 < nchunks) {
            load_stage((c + 1) & 1, (c + 1) * 32);
            cp_commit();
            cp_wait<1>();
        } else {
            cp_wait<0>();
        }
        __syncthreads();
        compute_stage(c & 1);
        __syncthreads();
    }

    // ------- epilogue: write from fragments -------
    const long long zc = (long long)z * sc;
    #pragma unroll
    for (int im = 0; im < 4; im++) {
        #pragma unroll
        for (int in = 0; in < 4; in++) {
            const int mr = m0 + wm0 + im * 16 + (lane >> 2);
            const int nc = n0 + wn0 + in * 8 + ((lane & 3) << 1);
            float bx = 0.0f, by = 0.0f;
            if (bias) { float2 bb = *reinterpret_cast<const float2*>(&bias[nc]); bx = bb.x; by = bb.y; }
            const float v0 = acc[im][in][0] + bx;
            const float v1 = acc[im][in][1] + by;
            const float v2 = acc[im][in][2] + bx;
            const float v3 = acc[im][in][3] + by;
            const long long o0 = zc + (long long)mr * ldc + nc;
            const long long o1 = zc + (long long)(mr + 8) * ldc + nc;
            if (OMODE == 0) {
                *reinterpret_cast<float2*>(&cf[o0]) = make_float2(v0, v1);
                *reinterpret_cast<float2*>(&cf[o1]) = make_float2(v2, v3);
            } else {
                __nv_bfloat16 h0, l0, h1, l1, h2, l2, h3, l3;
                split2(v0, h0, l0); split2(v1, h1, l1);
                split2(v2, h2, l2); split2(v3, h3, l3);
                *reinterpret_cast<__nv_bfloat162*>(&ch[o0]) = __nv_bfloat162(h0, h1);
                *reinterpret_cast<__nv_bfloat162*>(&ch[o1]) = __nv_bfloat162(h2, h3);
                *reinterpret_cast<__nv_bfloat162*>(&cl[o0]) = __nv_bfloat162(l0, l1);
                *reinterpret_cast<__nv_bfloat162*>(&cl[o1]) = __nv_bfloat162(l2, l3);
            }
        }
    }
}

// ===================== glue kernels =====================
__global__ __launch_bounds__(256)
void split_kernel(const float* __restrict__ src,
                  __nv_bfloat16* __restrict__ hi, __nv_bfloat16* __restrict__ lo)
{
    const size_t i = ((size_t)blockIdx.x * 256 + threadIdx.x) * 4;
    float4 v = *reinterpret_cast<const float4*>(src + i);
    __nv_bfloat16 h0,l0,h1,l1,h2,l2,h3,l3;
    split2(v.x, h0, l0); split2(v.y, h1, l1); split2(v.z, h2, l2); split2(v.w, h3, l3);
    *reinterpret_cast<__nv_bfloat162*>(hi + i)     = __nv_bfloat162(h0, h1);
    *reinterpret_cast<__nv_bfloat162*>(hi + i + 2) = __nv_bfloat162(h2, h3);
    *reinterpret_cast<__nv_bfloat162*>(lo + i)     = __nv_bfloat162(l0, l1);
    *reinterpret_cast<__nv_bfloat162*>(lo + i + 2) = __nv_bfloat162(l2, l3);
}

// row softmax (len 2048) -> bf16 hi/lo pair
__global__ __launch_bounds__(256)
void softmax_split_kernel(const float* __restrict__ S,
                          __nv_bfloat16* __restrict__ ah, __nv_bfloat16* __restrict__ al)
{
    const size_t row = blockIdx.x;
    const float* p = S + row * SEQ;
    const int tid = threadIdx.x;
    __shared__ float red[8];

    float v[8];
    float mx = -1e30f;
    #pragma unroll
    for (int i = 0; i < 8; i++) { v[i] = p[i * 256 + tid]; mx = fmaxf(mx, v[i]); }
    #pragma unroll
    for (int o = 16; o; o >>= 1) mx = fmaxf(mx, __shfl_xor_sync(0xffffffffu, mx, o));
    if ((tid & 31) == 0) red[tid >> 5] = mx;
    __syncthreads();
    mx = red[0];
    #pragma unroll
    for (int i = 1; i < 8; i++) mx = fmaxf(mx, red[i]);
    __syncthreads();

    float s = 0.0f;
    #pragma unroll
    for (int i = 0; i < 8; i++) { v[i] = expf(v[i] - mx); s += v[i]; }
    #pragma unroll
    for (int o = 16; o; o >>= 1) s += __shfl_xor_sync(0xffffffffu, s, o);
    if ((tid & 31) == 0) red[tid >> 5] = s;
    __syncthreads();
    s = red[0];
    #pragma unroll
    for (int i = 1; i < 8; i++) s += red[i];

    const float inv = 1.0f / s;
    #pragma unroll
    for (int i = 0; i < 8; i++) {
        __nv_bfloat16 h, l;
        split2(v[i] * inv, h, l);
        ah[row * SEQ + i * 256 + tid] = h;
        al[row * SEQ + i * 256 + tid] = l;
    }
}

// gated = ctx * sigmoid(gpre) -> bf16 hi/lo pair
__global__ __launch_bounds__(256)
void gate_split_kernel(const float* __restrict__ ctx, const float* __restrict__ gp,
                       __nv_bfloat16* __restrict__ gh, __nv_bfloat16* __restrict__ gl)
{
    const size_t i = ((size_t)blockIdx.x * 256 + threadIdx.x) * 4;
    float4 c = *reinterpret_cast<const float4*>(ctx + i);
    float4 g = *reinterpret_cast<const float4*>(gp + i);
    float o0 = c.x / (1.0f + expf(-g.x));
    float o1 = c.y / (1.0f + expf(-g.y));
    float o2 = c.z / (1.0f + expf(-g.z));
    float o3 = c.w / (1.0f + expf(-g.w));
    __nv_bfloat16 h0,l0,h1,l1,h2,l2,h3,l3;
    split2(o0, h0, l0); split2(o1, h1, l1); split2(o2, h2, l2); split2(o3, h3, l3);
    *reinterpret_cast<__nv_bfloat162*>(gh + i)     = __nv_bfloat162(h0, h1);
    *reinterpret_cast<__nv_bfloat162*>(gh + i + 2) = __nv_bfloat162(h2, h3);
    *reinterpret_cast<__nv_bfloat162*>(gl + i)     = __nv_bfloat162(l0, l1);
    *reinterpret_cast<__nv_bfloat162*>(gl + i + 2) = __nv_bfloat162(l2, l3);
}

// ===================== host =====================
extern "C" void kernel_launch(void* const* d_in, const int* in_sizes, int n_in,
                              void* d_out, int out_size)
{
    (void)in_sizes; (void)n_in; (void)out_size;

    const float* queries = (const float*)d_in[0];
    const float* keys    = (const float*)d_in[1];
    const float* values  = (const float*)d_in[2];
    const float* Wq = (const float*)d_in[3];
    const float* bq = (const float*)d_in[4];
    const float* Wk = (const float*)d_in[5];
    const float* bk = (const float*)d_in[6];
    const float* Wv = (const float*)d_in[7];
    const float* bv = (const float*)d_in[8];
    const float* Wg = (const float*)d_in[9];
    const float* bg = (const float*)d_in[10];
    const float* Wo = (const float*)d_in[11];
    const float* bo = (const float*)d_in[12];
    float* out = (float*)d_out;

    void *Qh,*Ql,*Kh,*Kl,*Vh,*Vl,*qph,*qpl,*kph,*kpl,*vph,*vpl,*gch,*gcl,*ah,*al;
    void *scores,*gpre,*ctx,*Wbase;
    cudaGetSymbolAddress(&Qh, g_Qh);   cudaGetSymbolAddress(&Ql, g_Ql);
    cudaGetSymbolAddress(&Kh, g_Kh);   cudaGetSymbolAddress(&Kl, g_Kl);
    cudaGetSymbolAddress(&Vh, g_Vh);   cudaGetSymbolAddress(&Vl, g_Vl);
    cudaGetSymbolAddress(&qph, g_qph); cudaGetSymbolAddress(&qpl, g_qpl);
    cudaGetSymbolAddress(&kph, g_kph); cudaGetSymbolAddress(&kpl, g_kpl);
    cudaGetSymbolAddress(&vph, g_vph); cudaGetSymbolAddress(&vpl, g_vpl);
    cudaGetSymbolAddress(&gch, g_gch); cudaGetSymbolAddress(&gcl, g_gcl);
    cudaGetSymbolAddress(&ah, g_ah);   cudaGetSymbolAddress(&al, g_al);
    cudaGetSymbolAddress(&scores, g_scores);
    cudaGetSymbolAddress(&gpre, g_gpre);
    cudaGetSymbolAddress(&ctx, g_ctx);
    cudaGetSymbolAddress(&Wbase, g_W);
    __nv_bfloat16* Wt = (__nv_bfloat16*)Wbase;   // 10 x DIM*DIM, layout [k][n]

    cudaFuncSetAttribute(hgemm<true,  0>, cudaFuncAttributeMaxDynamicSharedMemorySize, GEMM_SMEM);
    cudaFuncSetAttribute(hgemm<true,  1>, cudaFuncAttributeMaxDynamicSharedMemorySize, GEMM_SMEM);
    cudaFuncSetAttribute(hgemm<false, 0>, cudaFuncAttributeMaxDynamicSharedMemorySize, GEMM_SMEM);

    // ---- 1. split inputs and weights (weights stay [k][n], no transpose) ----
    {
        const unsigned nb = (unsigned)(NBF / 4 / 256);
        split_kernel<<<nb, 256>>>(queries, (__nv_bfloat16*)Qh, (__nv_bfloat16*)Ql);
        split_kernel<<<nb, 256>>>(keys,    (__nv_bfloat16*)Kh, (__nv_bfloat16*)Kl);
        split_kernel<<<nb, 256>>>(values,  (__nv_bfloat16*)Vh, (__nv_bfloat16*)Vl);
        const unsigned nw = (unsigned)((size_t)DIM * DIM / 4 / 256);
        split_kernel<<<nw, 256>>>(Wq, Wt + 0 * (size_t)DIM * DIM, Wt + 1 * (size_t)DIM * DIM);
        split_kernel<<<nw, 256>>>(Wk, Wt + 2 * (size_t)DIM * DIM, Wt + 3 * (size_t)DIM * DIM);
        split_kernel<<<nw, 256>>>(Wv, Wt + 4 * (size_t)DIM * DIM, Wt + 5 * (size_t)DIM * DIM);
        split_kernel<<<nw, 256>>>(Wg, Wt + 6 * (size_t)DIM * DIM, Wt + 7 * (size_t)DIM * DIM);
        split_kernel<<<nw, 256>>>(Wo, Wt + 8 * (size_t)DIM * DIM, Wt + 9 * (size_t)DIM * DIM);
    }

    // ---- 2. projections: X @ W + b   (B = W, [k][n] -> TRANSB=true) ----
    {
        dim3 g(DIM / 128, MTOT / 128, 1);
        hgemm<true, 1><<<g, 256, GEMM_SMEM>>>(
            (const __nv_bfloat16*)Qh, (const __nv_bfloat16*)Ql,
            Wt + 0 * (size_t)DIM * DIM, Wt + 1 * (size_t)DIM * DIM,
            nullptr, (__nv_bfloat16*)qph, (__nv_bfloat16*)qpl, bq,
            DIM, DIM, DIM, DIM, 0, 0, 0);
        hgemm<true, 1><<<g, 256, GEMM_SMEM>>>(
            (const __nv_bfloat16*)Kh, (const __nv_bfloat16*)Kl,
            Wt + 2 * (size_t)DIM * DIM, Wt + 3 * (size_t)DIM * DIM,
            nullptr, (__nv_bfloat16*)kph, (__nv_bfloat16*)kpl, bk,
            DIM, DIM, DIM, DIM, 0, 0, 0);
        hgemm<true, 1><<<g, 256, GEMM_SMEM>>>(
            (const __nv_bfloat16*)Vh, (const __nv_bfloat16*)Vl,
            Wt + 4 * (size_t)DIM * DIM, Wt + 5 * (size_t)DIM * DIM,
            nullptr, (__nv_bfloat16*)vph, (__nv_bfloat16*)vpl, bv,
            DIM, DIM, DIM, DIM, 0, 0, 0);
        hgemm<true, 0><<<g, 256, GEMM_SMEM>>>(
            (const __nv_bfloat16*)Qh, (const __nv_bfloat16*)Ql,
            Wt + 6 * (size_t)DIM * DIM, Wt + 7 * (size_t)DIM * DIM,
            (float*)gpre, nullptr, nullptr, bg,
            DIM, DIM, DIM, DIM, 0, 0, 0);
    }

    // ---- 3. scores[b] = q[b] @ k[b]^T  (B = k, [n][k] -> TRANSB=false) ----
    {
        dim3 g(SEQ / 128, SEQ / 128, BATCH);
        hgemm<false, 0><<<g, 256, GEMM_SMEM>>>(
            (const __nv_bfloat16*)qph, (const __nv_bfloat16*)qpl,
            (const __nv_bfloat16*)kph, (const __nv_bfloat16*)kpl,
            (float*)scores, nullptr, nullptr, nullptr,
            DIM, DIM, SEQ, DIM,
            (long long)SEQ * DIM, (long long)SEQ * DIM, (long long)SEQ * SEQ);
    }

    // ---- 4. softmax -> bf16 pair ----
    softmax_split_kernel<<<BATCH * SEQ, 256>>>((const float*)scores,
        (__nv_bfloat16*)ah, (__nv_bfloat16*)al);

    // ---- 5. context[b] = attn[b] @ v[b]  (B = v, [k][n] -> TRANSB=true) ----
    {
        dim3 g(DIM / 128, SEQ / 128, BATCH);
        hgemm<true, 0><<<g, 256, GEMM_SMEM>>>(
            (const __nv_bfloat16*)ah, (const __nv_bfloat16*)al,
            (const __nv_bfloat16*)vph, (const __nv_bfloat16*)vpl,
            (float*)ctx, nullptr, nullptr, nullptr,
            SEQ, DIM, DIM, SEQ,
            (long long)SEQ * SEQ, (long long)SEQ * DIM, (long long)SEQ * DIM);
    }

    // ---- 6. gate ----
    gate_split_kernel<<<(unsigned)(NBF / 4 / 256), 256>>>(
        (const float*)ctx, (const float*)gpre, (__nv_bfloat16*)gch, (__nv_bfloat16*)gcl);

    // ---- 7. out = gated @ Wo + bo ----
    {
        dim3 g(DIM / 128, MTOT / 128, 1);
        hgemm<true, 0><<<g, 256, GEMM_SMEM>>>(
            (const __nv_bfloat16*)gch, (const __nv_bfloat16*)gcl,
            Wt + 8 * (size_t)DIM * DIM, Wt + 9 * (size_t)DIM * DIM,
            out, nullptr, nullptr, bo,
            DIM, DIM, DIM, DIM, 0, 0, 0);
    }
}

// round 5
// speedup vs baseline: 3.0630x; 1.0448x over previous
#include <cuda_runtime.h>
#include <cuda_bf16.h>
#include <math.h>
#include <stdint.h>

#define BATCH 8
#define SEQ   2048
#define DIM   1024
#define MTOT  (BATCH * SEQ)   // 16384

#define NBF ((size_t)MTOT * DIM)         // 16,777,216
#define NSC ((size_t)BATCH * SEQ * SEQ)  // 33,554,432

// ===================== scratch (no cudaMalloc allowed) =====================
__device__ __align__(1024) __nv_bfloat16 g_Qh[NBF], g_Ql[NBF];   // split inputs
__device__ __align__(1024) __nv_bfloat16 g_Kh[NBF], g_Kl[NBF];
__device__ __align__(1024) __nv_bfloat16 g_Vh[NBF], g_Vl[NBF];
__device__ __align__(1024) __nv_bfloat16 g_qph[NBF], g_qpl[NBF]; // q projection
__device__ __align__(1024) __nv_bfloat16 g_kph[NBF], g_kpl[NBF]; // k projection
__device__ __align__(1024) __nv_bfloat16 g_vph[NBF], g_vpl[NBF]; // v projection [s][d]
__device__ __align__(1024) __nv_bfloat16 g_gch[NBF], g_gcl[NBF]; // gated context
__device__ __align__(1024) __nv_bfloat16 g_ah[NSC], g_al[NSC];   // softmax(attn)
__device__ __align__(1024) __nv_bfloat16 g_W[10][DIM * DIM];     // W h/l x5, layout [k][n]
__device__ __align__(1024) float g_scores[NSC];
__device__ __align__(1024) float g_gpre[NBF];
__device__ __align__(1024) float g_ctx[NBF];

// ===================== PTX wrappers (baseline sm_80+ features only) =========
__device__ __forceinline__ uint32_t smem_u32(const void* p) {
    uint32_t a;
    asm("{ .reg .u64 t; cvta.to.shared.u64 t, %1; cvt.u32.u64 %0, t; }" : "=r"(a) : "l"(p));
    return a;
}
__device__ __forceinline__ void cpa16(uint32_t dst, const void* src) {
    asm volatile("cp.async.cg.shared.global [%0], [%1], 16;" :: "r"(dst), "l"(src));
}
__device__ __forceinline__ void cp_commit() {
    asm volatile("cp.async.commit_group;" ::: "memory");
}
template <int N>
__device__ __forceinline__ void cp_wait() {
    asm volatile("cp.async.wait_group %0;" :: "n"(N) : "memory");
}
__device__ __forceinline__ void ldm4(uint32_t r[4], uint32_t addr) {
    asm volatile("ldmatrix.sync.aligned.m8n8.x4.shared.b16 {%0,%1,%2,%3}, [%4];"
                 : "=r"(r[0]), "=r"(r[1]), "=r"(r[2]), "=r"(r[3]) : "r"(addr));
}
__device__ __forceinline__ void ldm4t(uint32_t r[4], uint32_t addr) {
    asm volatile("ldmatrix.sync.aligned.m8n8.x4.trans.shared.b16 {%0,%1,%2,%3}, [%4];"
                 : "=r"(r[0]), "=r"(r[1]), "=r"(r[2]), "=r"(r[3]) : "r"(addr));
}
__device__ __forceinline__ void mma16816(float c[4],
                                         const uint32_t a[4],
                                         uint32_t b0, uint32_t b1) {
    asm volatile(
        "mma.sync.aligned.m16n8k16.row.col.f32.bf16.bf16.f32 "
        "{%0,%1,%2,%3}, {%4,%5,%6,%7}, {%8,%9}, {%0,%1,%2,%3};"
        : "+f"(c[0]), "+f"(c[1]), "+f"(c[2]), "+f"(c[3])
        : "r"(a[0]), "r"(a[1]), "r"(a[2]), "r"(a[3]), "r"(b0), "r"(b1));
}
__device__ __forceinline__ void split2(float x, __nv_bfloat16& h, __nv_bfloat16& l) {
    h = __float2bfloat16(x);
    l = __float2bfloat16(x - __bfloat162float(h));
}

// ===================== bf16x3 HMMA GEMM =====================
// D(128x128 tile) = A @ op(B), fp32 accumulate, 3 MMA passes (hh + hl + lh).
// 128 threads, 4 warps, warp tile 64x64 (MMA:ldmatrix = 6:1).
// TRANSB=false: B stored [n][k]. TRANSB=true: B stored [k][n].
// OMODE 0: fp32 out (+bias). OMODE 1: bf16 hi/lo pair out (+bias).
#define PA_E   40            // A / B-nontrans row pitch (elems): 32 data + 8 pad
#define PA_B   (PA_E * 2)    // 80 bytes
#define PBT_E  136           // B-trans row pitch (elems): 128 data + 8 pad
#define PBT_B  (PBT_E * 2)   // 272 bytes
#define MAT_BYTES   10240
#define STAGE_BYTES (4 * MAT_BYTES)           // Ah, Al, Bh, Bl
#define GEMM_SMEM   (2 * STAGE_BYTES)         // double buffered = 81920 B

template <bool TRANSB, int OMODE>
__global__ void __launch_bounds__(128, 2)
hgemm(const __nv_bfloat16* __restrict__ gAh, const __nv_bfloat16* __restrict__ gAl,
      const __nv_bfloat16* __restrict__ gBh, const __nv_bfloat16* __restrict__ gBl,
      float* __restrict__ cf,
      __nv_bfloat16* __restrict__ ch, __nv_bfloat16* __restrict__ cl,
      const float* __restrict__ bias,
      int lda, int ldb, int ldc, int K,
      long long sa, long long sb, long long sc)
{
    extern __shared__ __align__(128) char smem[];
    const uint32_t sbase = smem_u32(smem);

    const int tid  = threadIdx.x;
    const int wid  = tid >> 5;
    const int lane = tid & 31;
    const int m0   = blockIdx.y * 128;
    const int n0   = blockIdx.x * 128;
    const int z    = blockIdx.z;

    gAh += (long long)z * sa;  gAl += (long long)z * sa;
    gBh += (long long)z * sb;  gBl += (long long)z * sb;

    const int wm0 = (wid >> 1) * 64;    // warp m offset
    const int wn0 = (wid & 1) * 64;     // warp n offset

    float acc[4][8][4];
    #pragma unroll
    for (int i = 0; i < 4; i++)
        #pragma unroll
        for (int j = 0; j < 8; j++)
            #pragma unroll
            for (int r = 0; r < 4; r++) acc[i][j][r] = 0.0f;

    const int nchunks = K >> 5;

    // ------- stage loader (128 threads) -------
    auto load_stage = [&](int s, int k0) {
        const uint32_t st = sbase + s * STAGE_BYTES;
        #pragma unroll
        for (int j = 0; j < 4; j++) {
            const int c = tid + 128 * j;
            {   // A hi/lo: 128 rows x 32 cols
                const int row = c >> 2, col = c & 3;
                const uint32_t so = st + row * PA_B + col * 16;
                const long long go = (long long)(m0 + row) * lda + k0 + col * 8;
                cpa16(so,             gAh + go);
                cpa16(so + MAT_BYTES, gAl + go);
            }
            if (TRANSB) {   // B: 32 rows (k) x 128 cols (n)
                const int row = c >> 4, col = c & 15;
                const uint32_t so = st + 2 * MAT_BYTES + row * PBT_B + col * 16;
                const long long go = (long long)(k0 + row) * ldb + n0 + col * 8;
                cpa16(so,             gBh + go);
                cpa16(so + MAT_BYTES, gBl + go);
            } else {        // B: 128 rows (n) x 32 cols (k)
                const int row = c >> 2, col = c & 3;
                const uint32_t so = st + 2 * MAT_BYTES + row * PA_B + col * 16;
                const long long go = (long long)(n0 + row) * ldb + k0 + col * 8;
                cpa16(so,             gBh + go);
                cpa16(so + MAT_BYTES, gBl + go);
            }
        }
    };

    // ------- compute one stage -------
    auto compute_stage = [&](int s) {
        const uint32_t ab = sbase + s * STAGE_BYTES;
        const uint32_t bb = ab + 2 * MAT_BYTES;
        #pragma unroll
        for (int ks = 0; ks < 32; ks += 16) {
            uint32_t ah[4][4], al[4][4];
            #pragma unroll
            for (int im = 0; im < 4; im++) {
                const uint32_t addr = ab
                    + (wm0 + im * 16 + (lane & 15)) * PA_B
                    + (ks + ((lane >> 4) << 3)) * 2;
                ldm4(ah[im], addr);
                ldm4(al[im], addr + MAT_BYTES);
            }
            #pragma unroll
            for (int half = 0; half < 4; half++) {   // n-tiles 2*half, 2*half+1
                const int nb = wn0 + half * 16;
                uint32_t rh[4], rl[4];
                if (TRANSB) {
                    const int krow = ks + (lane & 7) + (((lane >> 3) & 1) << 3);
                    const int ncol = nb + ((lane >> 4) << 3);
                    const uint32_t addr = bb + krow * PBT_B + ncol * 2;
                    ldm4t(rh, addr);
                    ldm4t(rl, addr + MAT_BYTES);
                } else {
                    const int nrow = nb + (lane & 7) + ((lane >> 4) << 3);
                    const int kcol = ks + (((lane >> 3) & 1) << 3);
                    const uint32_t addr = bb + nrow * PA_B + kcol * 2;
                    ldm4(rh, addr);
                    ldm4(rl, addr + MAT_BYTES);
                }
                #pragma unroll
                for (int im = 0; im < 4; im++) {
                    mma16816(acc[im][2*half],   ah[im], rh[0], rh[1]);
                    mma16816(acc[im][2*half],   ah[im], rl[0], rl[1]);
                    mma16816(acc[im][2*half],   al[im], rh[0], rh[1]);
                    mma16816(acc[im][2*half+1], ah[im], rh[2], rh[3]);
                    mma16816(acc[im][2*half+1], ah[im], rl[2], rl[3]);
                    mma16816(acc[im][2*half+1], al[im], rh[2], rh[3]);
                }
            }
        }
    };

    // ------- pipeline -------
    load_stage(0, 0);
    cp_commit();
    for (int c = 0; c < nchunks; c++) {
        if (c + 1 < nchunks) {
            load_stage((c + 1) & 1, (c + 1) * 32);
            cp_commit();
            cp_wait<1>();
        } else {
            cp_wait<0>();
        }
        __syncthreads();
        compute_stage(c & 1);
        __syncthreads();
    }

    // ------- epilogue: write from fragments -------
    const long long zc = (long long)z * sc;
    #pragma unroll
    for (int im = 0; im < 4; im++) {
        #pragma unroll
        for (int in = 0; in < 8; in++) {
            const int mr = m0 + wm0 + im * 16 + (lane >> 2);
            const int nc = n0 + wn0 + in * 8 + ((lane & 3) << 1);
            float bx = 0.0f, by = 0.0f;
            if (bias) { float2 bb = *reinterpret_cast<const float2*>(&bias[nc]); bx = bb.x; by = bb.y; }
            const float v0 = acc[im][in][0] + bx;
            const float v1 = acc[im][in][1] + by;
            const float v2 = acc[im][in][2] + bx;
            const float v3 = acc[im][in][3] + by;
            const long long o0 = zc + (long long)mr * ldc + nc;
            const long long o1 = zc + (long long)(mr + 8) * ldc + nc;
            if (OMODE == 0) {
                *reinterpret_cast<float2*>(&cf[o0]) = make_float2(v0, v1);
                *reinterpret_cast<float2*>(&cf[o1]) = make_float2(v2, v3);
            } else {
                __nv_bfloat16 h0, l0, h1, l1, h2, l2, h3, l3;
                split2(v0, h0, l0); split2(v1, h1, l1);
                split2(v2, h2, l2); split2(v3, h3, l3);
                *reinterpret_cast<__nv_bfloat162*>(&ch[o0]) = __nv_bfloat162(h0, h1);
                *reinterpret_cast<__nv_bfloat162*>(&ch[o1]) = __nv_bfloat162(h2, h3);
                *reinterpret_cast<__nv_bfloat162*>(&cl[o0]) = __nv_bfloat162(l0, l1);
                *reinterpret_cast<__nv_bfloat162*>(&cl[o1]) = __nv_bfloat162(l2, l3);
            }
        }
    }
}

// ===================== glue kernels =====================
__global__ __launch_bounds__(256)
void split_kernel(const float* __restrict__ src,
                  __nv_bfloat16* __restrict__ hi, __nv_bfloat16* __restrict__ lo)
{
    const size_t i = ((size_t)blockIdx.x * 256 + threadIdx.x) * 4;
    float4 v = *reinterpret_cast<const float4*>(src + i);
    __nv_bfloat16 h0,l0,h1,l1,h2,l2,h3,l3;
    split2(v.x, h0, l0); split2(v.y, h1, l1); split2(v.z, h2, l2); split2(v.w, h3, l3);
    *reinterpret_cast<__nv_bfloat162*>(hi + i)     = __nv_bfloat162(h0, h1);
    *reinterpret_cast<__nv_bfloat162*>(hi + i + 2) = __nv_bfloat162(h2, h3);
    *reinterpret_cast<__nv_bfloat162*>(lo + i)     = __nv_bfloat162(l0, l1);
    *reinterpret_cast<__nv_bfloat162*>(lo + i + 2) = __nv_bfloat162(l2, l3);
}

// row softmax (len 2048) -> bf16 hi/lo pair
__global__ __launch_bounds__(256)
void softmax_split_kernel(const float* __restrict__ S,
                          __nv_bfloat16* __restrict__ ah, __nv_bfloat16* __restrict__ al)
{
    const size_t row = blockIdx.x;
    const float* p = S + row * SEQ;
    const int tid = threadIdx.x;
    __shared__ float red[8];

    float v[8];
    float mx = -1e30f;
    #pragma unroll
    for (int i = 0; i < 8; i++) { v[i] = p[i * 256 + tid]; mx = fmaxf(mx, v[i]); }
    #pragma unroll
    for (int o = 16; o; o >>= 1) mx = fmaxf(mx, __shfl_xor_sync(0xffffffffu, mx, o));
    if ((tid & 31) == 0) red[tid >> 5] = mx;
    __syncthreads();
    mx = red[0];
    #pragma unroll
    for (int i = 1; i < 8; i++) mx = fmaxf(mx, red[i]);
    __syncthreads();

    float s = 0.0f;
    #pragma unroll
    for (int i = 0; i < 8; i++) { v[i] = expf(v[i] - mx); s += v[i]; }
    #pragma unroll
    for (int o = 16; o; o >>= 1) s += __shfl_xor_sync(0xffffffffu, s, o);
    if ((tid & 31) == 0) red[tid >> 5] = s;
    __syncthreads();
    s = red[0];
    #pragma unroll
    for (int i = 1; i < 8; i++) s += red[i];

    const float inv = 1.0f / s;
    #pragma unroll
    for (int i = 0; i < 8; i++) {
        __nv_bfloat16 h, l;
        split2(v[i] * inv, h, l);
        ah[row * SEQ + i * 256 + tid] = h;
        al[row * SEQ + i * 256 + tid] = l;
    }
}

// gated = ctx * sigmoid(gpre) -> bf16 hi/lo pair
__global__ __launch_bounds__(256)
void gate_split_kernel(const float* __restrict__ ctx, const float* __restrict__ gp,
                       __nv_bfloat16* __restrict__ gh, __nv_bfloat16* __restrict__ gl)
{
    const size_t i = ((size_t)blockIdx.x * 256 + threadIdx.x) * 4;
    float4 c = *reinterpret_cast<const float4*>(ctx + i);
    float4 g = *reinterpret_cast<const float4*>(gp + i);
    float o0 = c.x / (1.0f + expf(-g.x));
    float o1 = c.y / (1.0f + expf(-g.y));
    float o2 = c.z / (1.0f + expf(-g.z));
    float o3 = c.w / (1.0f + expf(-g.w));
    __nv_bfloat16 h0,l0,h1,l1,h2,l2,h3,l3;
    split2(o0, h0, l0); split2(o1, h1, l1); split2(o2, h2, l2); split2(o3, h3, l3);
    *reinterpret_cast<__nv_bfloat162*>(gh + i)     = __nv_bfloat162(h0, h1);
    *reinterpret_cast<__nv_bfloat162*>(gh + i + 2) = __nv_bfloat162(h2, h3);
    *reinterpret_cast<__nv_bfloat162*>(gl + i)     = __nv_bfloat162(l0, l1);
    *reinterpret_cast<__nv_bfloat162*>(gl + i + 2) = __nv_bfloat162(l2, l3);
}

// ===================== host =====================
extern "C" void kernel_launch(void* const* d_in, const int* in_sizes, int n_in,
                              void* d_out, int out_size)
{
    (void)in_sizes; (void)n_in; (void)out_size;

    const float* queries = (const float*)d_in[0];
    const float* keys    = (const float*)d_in[1];
    const float* values  = (const float*)d_in[2];
    const float* Wq = (const float*)d_in[3];
    const float* bq = (const float*)d_in[4];
    const float* Wk = (const float*)d_in[5];
    const float* bk = (const float*)d_in[6];
    const float* Wv = (const float*)d_in[7];
    const float* bv = (const float*)d_in[8];
    const float* Wg = (const float*)d_in[9];
    const float* bg = (const float*)d_in[10];
    const float* Wo = (const float*)d_in[11];
    const float* bo = (const float*)d_in[12];
    float* out = (float*)d_out;

    void *Qh,*Ql,*Kh,*Kl,*Vh,*Vl,*qph,*qpl,*kph,*kpl,*vph,*vpl,*gch,*gcl,*ah,*al;
    void *scores,*gpre,*ctx,*Wbase;
    cudaGetSymbolAddress(&Qh, g_Qh);   cudaGetSymbolAddress(&Ql, g_Ql);
    cudaGetSymbolAddress(&Kh, g_Kh);   cudaGetSymbolAddress(&Kl, g_Kl);
    cudaGetSymbolAddress(&Vh, g_Vh);   cudaGetSymbolAddress(&Vl, g_Vl);
    cudaGetSymbolAddress(&qph, g_qph); cudaGetSymbolAddress(&qpl, g_qpl);
    cudaGetSymbolAddress(&kph, g_kph); cudaGetSymbolAddress(&kpl, g_kpl);
    cudaGetSymbolAddress(&vph, g_vph); cudaGetSymbolAddress(&vpl, g_vpl);
    cudaGetSymbolAddress(&gch, g_gch); cudaGetSymbolAddress(&gcl, g_gcl);
    cudaGetSymbolAddress(&ah, g_ah);   cudaGetSymbolAddress(&al, g_al);
    cudaGetSymbolAddress(&scores, g_scores);
    cudaGetSymbolAddress(&gpre, g_gpre);
    cudaGetSymbolAddress(&ctx, g_ctx);
    cudaGetSymbolAddress(&Wbase, g_W);
    __nv_bfloat16* Wt = (__nv_bfloat16*)Wbase;   // 10 x DIM*DIM, layout [k][n]

    cudaFuncSetAttribute(hgemm<true,  0>, cudaFuncAttributeMaxDynamicSharedMemorySize, GEMM_SMEM);
    cudaFuncSetAttribute(hgemm<true,  1>, cudaFuncAttributeMaxDynamicSharedMemorySize, GEMM_SMEM);
    cudaFuncSetAttribute(hgemm<false, 0>, cudaFuncAttributeMaxDynamicSharedMemorySize, GEMM_SMEM);

    // ---- 1. split inputs and weights (weights stay [k][n], no transpose) ----
    {
        const unsigned nb = (unsigned)(NBF / 4 / 256);
        split_kernel<<<nb, 256>>>(queries, (__nv_bfloat16*)Qh, (__nv_bfloat16*)Ql);
        split_kernel<<<nb, 256>>>(keys,    (__nv_bfloat16*)Kh, (__nv_bfloat16*)Kl);
        split_kernel<<<nb, 256>>>(values,  (__nv_bfloat16*)Vh, (__nv_bfloat16*)Vl);
        const unsigned nw = (unsigned)((size_t)DIM * DIM / 4 / 256);
        split_kernel<<<nw, 256>>>(Wq, Wt + 0 * (size_t)DIM * DIM, Wt + 1 * (size_t)DIM * DIM);
        split_kernel<<<nw, 256>>>(Wk, Wt + 2 * (size_t)DIM * DIM, Wt + 3 * (size_t)DIM * DIM);
        split_kernel<<<nw, 256>>>(Wv, Wt + 4 * (size_t)DIM * DIM, Wt + 5 * (size_t)DIM * DIM);
        split_kernel<<<nw, 256>>>(Wg, Wt + 6 * (size_t)DIM * DIM, Wt + 7 * (size_t)DIM * DIM);
        split_kernel<<<nw, 256>>>(Wo, Wt + 8 * (size_t)DIM * DIM, Wt + 9 * (size_t)DIM * DIM);
    }

    // ---- 2. projections: X @ W + b   (B = W, [k][n] -> TRANSB=true) ----
    {
        dim3 g(DIM / 128, MTOT / 128, 1);
        hgemm<true, 1><<<g, 128, GEMM_SMEM>>>(
            (const __nv_bfloat16*)Qh, (const __nv_bfloat16*)Ql,
            Wt + 0 * (size_t)DIM * DIM, Wt + 1 * (size_t)DIM * DIM,
            nullptr, (__nv_bfloat16*)qph, (__nv_bfloat16*)qpl, bq,
            DIM, DIM, DIM, DIM, 0, 0, 0);
        hgemm<true, 1><<<g, 128, GEMM_SMEM>>>(
            (const __nv_bfloat16*)Kh, (const __nv_bfloat16*)Kl,
            Wt + 2 * (size_t)DIM * DIM, Wt + 3 * (size_t)DIM * DIM,
            nullptr, (__nv_bfloat16*)kph, (__nv_bfloat16*)kpl, bk,
            DIM, DIM, DIM, DIM, 0, 0, 0);
        hgemm<true, 1><<<g, 128, GEMM_SMEM>>>(
            (const __nv_bfloat16*)Vh, (const __nv_bfloat16*)Vl,
            Wt + 4 * (size_t)DIM * DIM, Wt + 5 * (size_t)DIM * DIM,
            nullptr, (__nv_bfloat16*)vph, (__nv_bfloat16*)vpl, bv,
            DIM, DIM, DIM, DIM, 0, 0, 0);
        hgemm<true, 0><<<g, 128, GEMM_SMEM>>>(
            (const __nv_bfloat16*)Qh, (const __nv_bfloat16*)Ql,
            Wt + 6 * (size_t)DIM * DIM, Wt + 7 * (size_t)DIM * DIM,
            (float*)gpre, nullptr, nullptr, bg,
            DIM, DIM, DIM, DIM, 0, 0, 0);
    }

    // ---- 3. scores[b] = q[b] @ k[b]^T  (B = k, [n][k] -> TRANSB=false) ----
    {
        dim3 g(SEQ / 128, SEQ / 128, BATCH);
        hgemm<false, 0><<<g, 128, GEMM_SMEM>>>(
            (const __nv_bfloat16*)qph, (const __nv_bfloat16*)qpl,
            (const __nv_bfloat16*)kph, (const __nv_bfloat16*)kpl,
            (float*)scores, nullptr, nullptr, nullptr,
            DIM, DIM, SEQ, DIM,
            (long long)SEQ * DIM, (long long)SEQ * DIM, (long long)SEQ * SEQ);
    }

    // ---- 4. softmax -> bf16 pair ----
    softmax_split_kernel<<<BATCH * SEQ, 256>>>((const float*)scores,
        (__nv_bfloat16*)ah, (__nv_bfloat16*)al);

    // ---- 5. context[b] = attn[b] @ v[b]  (B = v, [k][n] -> TRANSB=true) ----
    {
        dim3 g(DIM / 128, SEQ / 128, BATCH);
        hgemm<true, 0><<<g, 128, GEMM_SMEM>>>(
            (const __nv_bfloat16*)ah, (const __nv_bfloat16*)al,
            (const __nv_bfloat16*)vph, (const __nv_bfloat16*)vpl,
            (float*)ctx, nullptr, nullptr, nullptr,
            SEQ, DIM, DIM, SEQ,
            (long long)SEQ * SEQ, (long long)SEQ * DIM, (long long)SEQ * DIM);
    }

    // ---- 6. gate ----
    gate_split_kernel<<<(unsigned)(NBF / 4 / 256), 256>>>(
        (const float*)ctx, (const float*)gpre, (__nv_bfloat16*)gch, (__nv_bfloat16*)gcl);

    // ---- 7. out = gated @ Wo + bo ----
    {
        dim3 g(DIM / 128, MTOT / 128, 1);
        hgemm<true, 0><<<g, 128, GEMM_SMEM>>>(
            (const __nv_bfloat16*)gch, (const __nv_bfloat16*)gcl,
            Wt + 8 * (size_t)DIM * DIM, Wt + 9 * (size_t)DIM * DIM,
            out, nullptr, nullptr, bo,
            DIM, DIM, DIM, DIM, 0, 0, 0);
    }
}